// round 2
// baseline (speedup 1.0000x reference)
#include <cuda_runtime.h>
#include <cuda_bf16.h>
#include <math.h>

#define TS_   256
#define CTS_  512
#define B_    64
#define H_    512
#define K_    10
#define H3_   1536
#define TB_   16384          // TS_*B_
#define LOG2E 1.44269504088896340736f

static const int OFF_ATTK = TB_ * H_;                 // 8388608
static const int OFF_ATTW = TB_ * H_ + TB_ * K_;      // 8552448

// ---------------- static device scratch ----------------
__device__ float    g_a   [TB_ * K_];
__device__ float    g_b2  [TB_ * K_];     // b_t * log2(e)
__device__ float    g_kinc[TB_ * K_];     // becomes cumulative k_t after k_cumsum
__device__ float    g_phi [TB_ * CTS_];
__device__ float    g_gi  [TB_ * H3_];
__device__ float    g_h   [2 * B_ * H_]; // ping-pong hidden state
__device__ unsigned g_barrier;

__device__ __forceinline__ float ex2f(float x) {
    float r; asm("ex2.approx.ftz.f32 %0, %1;" : "=f"(r) : "f"(x)); return r;
}
__device__ __forceinline__ float sigmf(float x) {
    return 1.0f / (1.0f + __expf(-x));
}

// ---------------- K0: init hidden + barrier ----------------
__global__ void k_init(const float* __restrict__ gru_init) {
    int i = blockIdx.x * 1024 + threadIdx.x;
    g_h[i] = gru_init[i];          // buffer 0 = h_{-1}
    if (i == 0) g_barrier = 0;
}

// ---------------- K1: a_t, b_t, kinc_t ----------------
// grid 2048 blocks x 256 threads; block handles 8 rows (t*64+b), warp = 1 row, lane = output o in [0,30)
__global__ __launch_bounds__(256) void k_abk(
    const float* __restrict__ inp,
    const float* __restrict__ Wa, const float* __restrict__ ba,
    const float* __restrict__ Wb, const float* __restrict__ bb,
    const float* __restrict__ Wk, const float* __restrict__ bk)
{
    __shared__ float xs[8 * 516];
    int tid = threadIdx.x;
    int r0 = blockIdx.x * 8;
    // stage 8 input rows
    #pragma unroll
    for (int c = 0; c < 4; c++) {
        int fi = c * 256 + tid;            // float4 index, 1024 total
        int r = fi >> 7, hq = fi & 127;
        float4 v = *(const float4*)&inp[(r0 + r) * 512 + hq * 4];
        *(float4*)&xs[r * 516 + hq * 4] = v;
    }
    __syncthreads();

    int r = tid >> 5, o = tid & 31;
    if (o >= 30) return;
    const float* wrow; float bias;
    if (o < 10)      { wrow = Wa + o * 512;        bias = ba[o]; }
    else if (o < 20) { wrow = Wb + (o - 10) * 512; bias = bb[o - 10]; }
    else             { wrow = Wk + (o - 20) * 512; bias = bk[o - 20]; }

    const float4* xp = (const float4*)&xs[r * 516];
    const float4* wp = (const float4*)wrow;
    float a0 = 0.f, a1 = 0.f, a2 = 0.f, a3 = 0.f;
    #pragma unroll 8
    for (int q = 0; q < 128; q++) {
        float4 x = xp[q];
        float4 w = __ldg(&wp[q]);
        a0 += x.x * w.x; a1 += x.y * w.y; a2 += x.z * w.z; a3 += x.w * w.w;
    }
    float v = expf((a0 + a1) + (a2 + a3) + bias);
    int row = r0 + r;
    if (o < 10)      g_a   [row * 10 + o]        = v;
    else if (o < 20) g_b2  [row * 10 + (o - 10)] = v * LOG2E;
    else             g_kinc[row * 10 + (o - 20)] = v;
}

// ---------------- K2: cumulative k_t + att_k output ----------------
__global__ void k_cumsum(const float* __restrict__ att_init, float* __restrict__ out) {
    int j = blockIdx.x * 128 + threadIdx.x;    // 640 sequences (b*10+k)
    if (j >= 640) return;
    float acc = att_init[j];
    #pragma unroll 8
    for (int t = 0; t < TS_; t++) {
        acc += g_kinc[t * 640 + j];
        g_kinc[t * 640 + j] = acc;
        out[OFF_ATTK + t * 640 + j] = acc;
    }
}

// ---------------- K3: phi[t,b,s] ----------------
__global__ __launch_bounds__(512) void k_phi() {
    __shared__ float sa[10], sb[10], sk[10];
    int row = blockIdx.x;                 // t*64+b
    int tid = threadIdx.x;
    if (tid < 10)       sa[tid]      = g_a   [row * 10 + tid];
    else if (tid < 20)  sb[tid - 10] = g_b2  [row * 10 + tid - 10];
    else if (tid < 30)  sk[tid - 20] = g_kinc[row * 10 + tid - 20];
    __syncthreads();
    float s = (float)tid;
    float acc = 0.f;
    #pragma unroll
    for (int k = 0; k < 10; k++) {
        float d = sk[k] - s;
        float e = sb[k] * d * d;          // b*log2e*d^2
        if (e < 30.f) acc += sa[k] * ex2f(-e);
    }
    g_phi[row * 512 + tid] = acc;
}

// ---------------- K4: w = phi @ c_inp (batched over b) ----------------
#define SST 68
__global__ __launch_bounds__(256) void k_gemm_w(
    const float* __restrict__ c_inp, float* __restrict__ outw)
{
    int b = blockIdx.z;
    const float* A  = g_phi + b * 512;   // (m=t,k=s): A[m*32768 + k]
    const float* Bp = c_inp + b * 512;   // (k=s,n=h): B[k*32768 + n]
    float*       C  = outw  + b * 512;   // C[m*32768 + n]
    int m0 = blockIdx.y * 64, n0 = blockIdx.x * 64;
    __shared__ float As[16 * SST], Bs[16 * SST];
    int tid = threadIdx.x;
    int ty = tid >> 4, tx = tid & 15;
    int lm = tid >> 2, lkq = tid & 3;    // A loader
    int lk = tid >> 4, lnq = tid & 15;   // B loader
    float acc[4][4] = {};
    for (int k0 = 0; k0 < 512; k0 += 16) {
        float4 av = *(const float4*)&A [(m0 + lm) * 32768 + k0 + lkq * 4];
        float4 bv = *(const float4*)&Bp[(k0 + lk) * 32768 + n0 + lnq * 4];
        __syncthreads();
        As[(lkq * 4 + 0) * SST + lm] = av.x;
        As[(lkq * 4 + 1) * SST + lm] = av.y;
        As[(lkq * 4 + 2) * SST + lm] = av.z;
        As[(lkq * 4 + 3) * SST + lm] = av.w;
        *(float4*)&Bs[lk * SST + lnq * 4] = bv;
        __syncthreads();
        #pragma unroll
        for (int kk = 0; kk < 16; kk++) {
            float4 a4 = *(const float4*)&As[kk * SST + ty * 4];
            float4 b4 = *(const float4*)&Bs[kk * SST + tx * 4];
            float avr[4] = {a4.x, a4.y, a4.z, a4.w};
            float bvr[4] = {b4.x, b4.y, b4.z, b4.w};
            #pragma unroll
            for (int i = 0; i < 4; i++)
                #pragma unroll
                for (int j = 0; j < 4; j++)
                    acc[i][j] += avr[i] * bvr[j];
        }
    }
    #pragma unroll
    for (int i = 0; i < 4; i++) {
        float4 v = make_float4(acc[i][0], acc[i][1], acc[i][2], acc[i][3]);
        *(float4*)&C[(m0 + ty * 4 + i) * 32768 + n0 + tx * 4] = v;
    }
}

// ---------------- K5: gi = w @ W_ih^T + b_ih ----------------
__global__ __launch_bounds__(256) void k_gemm_gi(
    const float* __restrict__ w, const float* __restrict__ W_ih,
    const float* __restrict__ b_ih)
{
    int m0 = blockIdx.y * 64, n0 = blockIdx.x * 64;
    __shared__ float As[16 * SST], Bs[16 * SST];
    int tid = threadIdx.x;
    int ty = tid >> 4, tx = tid & 15;
    int lm = tid >> 2, lkq = tid & 3;    // A loader (rows contiguous in k)
    int ln = tid >> 2;                   // B loader: W_ih rows contiguous in k
    float acc[4][4] = {};
    for (int k0 = 0; k0 < 512; k0 += 16) {
        float4 av = *(const float4*)&w   [(m0 + lm) * 512 + k0 + lkq * 4];
        float4 wv = *(const float4*)&W_ih[(n0 + ln) * 512 + k0 + lkq * 4];
        __syncthreads();
        As[(lkq * 4 + 0) * SST + lm] = av.x;
        As[(lkq * 4 + 1) * SST + lm] = av.y;
        As[(lkq * 4 + 2) * SST + lm] = av.z;
        As[(lkq * 4 + 3) * SST + lm] = av.w;
        Bs[(lkq * 4 + 0) * SST + ln] = wv.x;
        Bs[(lkq * 4 + 1) * SST + ln] = wv.y;
        Bs[(lkq * 4 + 2) * SST + ln] = wv.z;
        Bs[(lkq * 4 + 3) * SST + ln] = wv.w;
        __syncthreads();
        #pragma unroll
        for (int kk = 0; kk < 16; kk++) {
            float4 a4 = *(const float4*)&As[kk * SST + ty * 4];
            float4 b4 = *(const float4*)&Bs[kk * SST + tx * 4];
            float avr[4] = {a4.x, a4.y, a4.z, a4.w};
            float bvr[4] = {b4.x, b4.y, b4.z, b4.w};
            #pragma unroll
            for (int i = 0; i < 4; i++)
                #pragma unroll
                for (int j = 0; j < 4; j++)
                    acc[i][j] += avr[i] * bvr[j];
        }
    }
    float4 bias = *(const float4*)&b_ih[n0 + tx * 4];
    #pragma unroll
    for (int i = 0; i < 4; i++) {
        float4 v = make_float4(acc[i][0] + bias.x, acc[i][1] + bias.y,
                               acc[i][2] + bias.z, acc[i][3] + bias.w);
        *(float4*)&g_gi[(m0 + ty * 4 + i) * 1536 + n0 + tx * 4] = v;
    }
}

// ---------------- K6: persistent sequential GRU ----------------
// 128 blocks x 256 threads; block bid owns units u in [bid*4, bid*4+4)
// dyn smem: hs[64*516] + Wsm[12*516]
#define HS_ST 516
#define SMEM_GRU_FLOATS (64 * HS_ST + 12 * HS_ST)
#define SMEM_GRU_BYTES  (SMEM_GRU_FLOATS * 4)

__global__ __launch_bounds__(256, 1) void k_gru(
    const float* __restrict__ W_hh, const float* __restrict__ b_hh,
    float* __restrict__ out)
{
    extern __shared__ float smem[];
    float* hs  = smem;              // [64][516]
    float* Wsm = smem + 64 * HS_ST; // [12][516]: rows gate*4+ui
    int tid = threadIdx.x;
    int bid = blockIdx.x;

    // stage W_hh slice once (12 rows: r,z,n gates for 4 units)
    for (int idx = tid; idx < 12 * 512; idx += 256) {
        int rr = idx >> 9, hh = idx & 511;
        int gate = rr >> 2, ui = rr & 3;
        Wsm[rr * HS_ST + hh] = W_hh[(gate * 512 + bid * 4 + ui) * 512 + hh];
    }

    int b  = tid >> 2;
    int ui = tid & 3;
    int u  = bid * 4 + ui;
    float bhr = b_hh[u], bhz = b_hh[512 + u], bhn = b_hh[1024 + u];
    const float* wr = &Wsm[(0 + ui) * HS_ST];
    const float* wz = &Wsm[(4 + ui) * HS_ST];
    const float* wn = &Wsm[(8 + ui) * HS_ST];
    unsigned bar_target = 0;
    __syncthreads();

    for (int t = 0; t < TS_; t++) {
        // prefetch gi early
        const float* gp = g_gi + (t * 64 + b) * 1536 + u;
        float giR = __ldcs(gp);
        float giZ = __ldcs(gp + 512);
        float giN = __ldcs(gp + 1024);

        // stage h_{t-1} into smem (L2 reads; written by other SMs last step)
        const float* hsrc = g_h + (t & 1) * 32768;
        #pragma unroll
        for (int c = 0; c < 32; c++) {
            int i = (c * 256 + tid) * 4;
            float4 v = __ldcg((const float4*)(hsrc + i));
            *(float4*)&hs[(i >> 9) * HS_ST + (i & 511)] = v;
        }
        __syncthreads();

        float aR = 0.f, aZ = 0.f, aN = 0.f;
        const float* hrow = &hs[b * HS_ST];
        #pragma unroll 4
        for (int hh = 0; hh < 512; hh += 4) {
            float4 hv = *(const float4*)&hrow[hh];
            float4 r4 = *(const float4*)&wr[hh];
            float4 z4 = *(const float4*)&wz[hh];
            float4 n4 = *(const float4*)&wn[hh];
            aR += hv.x * r4.x; aR += hv.y * r4.y; aR += hv.z * r4.z; aR += hv.w * r4.w;
            aZ += hv.x * z4.x; aZ += hv.y * z4.y; aZ += hv.z * z4.z; aZ += hv.w * z4.w;
            aN += hv.x * n4.x; aN += hv.y * n4.y; aN += hv.z * n4.z; aN += hv.w * n4.w;
        }
        float hprev = hrow[u];
        float r = sigmf(giR + aR + bhr);
        float z = sigmf(giZ + aZ + bhz);
        float n = tanhf(giN + r * (aN + bhn));
        float hnew = (1.f - z) * n + z * hprev;

        g_h[((t + 1) & 1) * 32768 + b * 512 + u] = hnew;
        out[t * 32768 + b * 512 + u] = hnew;

        __threadfence();
        __syncthreads();
        if (tid == 0) {
            bar_target += 128;
            atomicAdd(&g_barrier, 1u);
            while (*((volatile unsigned*)&g_barrier) < bar_target) { __nanosleep(64); }
        }
        __syncthreads();
    }
}

// ---------------- host ----------------
extern "C" void kernel_launch(void* const* d_in, const int* in_sizes, int n_in,
                              void* d_out, int out_size)
{
    const float* c_inp    = (const float*)d_in[0];
    const float* inp      = (const float*)d_in[1];
    const float* gru_init = (const float*)d_in[2];
    const float* att_init = (const float*)d_in[3];
    const float* Wa = (const float*)d_in[4];  const float* ba = (const float*)d_in[5];
    const float* Wb = (const float*)d_in[6];  const float* bb = (const float*)d_in[7];
    const float* Wk = (const float*)d_in[8];  const float* bk = (const float*)d_in[9];
    const float* W_ih = (const float*)d_in[10]; const float* b_ih = (const float*)d_in[11];
    const float* W_hh = (const float*)d_in[12]; const float* b_hh = (const float*)d_in[13];
    float* out = (float*)d_out;

    cudaFuncSetAttribute(k_gru, cudaFuncAttributeMaxDynamicSharedMemorySize, SMEM_GRU_BYTES);

    k_init  <<<32, 1024>>>(gru_init);
    k_abk   <<<2048, 256>>>(inp, Wa, ba, Wb, bb, Wk, bk);
    k_cumsum<<<5, 128>>>(att_init, out);
    k_phi   <<<16384, 512>>>();
    k_gemm_w<<<dim3(8, 4, 64), 256>>>(c_inp, out + OFF_ATTW);
    k_gemm_gi<<<dim3(24, 256), 256>>>(out + OFF_ATTW, W_ih, b_ih);
    k_gru   <<<128, 256, SMEM_GRU_BYTES>>>(W_hh, b_hh, out);
}

// round 3
// speedup vs baseline: 1.4082x; 1.4082x over previous
#include <cuda_runtime.h>
#include <math.h>

#define TS_   256
#define CTS_  512
#define B_    64
#define H_    512
#define K_    10
#define H3_   1536
#define TB_   16384
#define LOG2E 1.44269504088896340736f

static const int OFF_ATTK = TB_ * H_;
static const int OFF_ATTW = TB_ * H_ + TB_ * K_;

typedef unsigned long long u64;

// ---------------- static device scratch ----------------
__device__ float    g_a   [TB_ * K_];
__device__ float    g_b2  [TB_ * K_];
__device__ float    g_kinc[TB_ * K_];
__device__ float    g_phi [TB_ * CTS_];
__device__ float    g_gi  [TB_ * H3_];
__device__ float    g_h   [2 * B_ * H_];
__device__ unsigned g_bar4[128];          // 4 barriers, padded

__device__ __forceinline__ float ex2f(float x) {
    float r; asm("ex2.approx.ftz.f32 %0, %1;" : "=f"(r) : "f"(x)); return r;
}
__device__ __forceinline__ float sigmf(float x) { return 1.0f / (1.0f + __expf(-x)); }

__device__ __forceinline__ u64 pack2(float lo, float hi) {
    u64 r; asm("mov.b64 %0, {%1, %2};" : "=l"(r) : "f"(lo), "f"(hi)); return r;
}
__device__ __forceinline__ void unpack2(u64 v, float& lo, float& hi) {
    asm("mov.b64 {%0, %1}, %2;" : "=f"(lo), "=f"(hi) : "l"(v));
}
__device__ __forceinline__ u64 ffma2(u64 a, u64 b, u64 c) {
    u64 d; asm("fma.rn.f32x2 %0, %1, %2, %3;" : "=l"(d) : "l"(a), "l"(b), "l"(c)); return d;
}

// ---------------- K0: init ----------------
__global__ void k_init(const float* __restrict__ gru_init) {
    int i = blockIdx.x * 1024 + threadIdx.x;
    g_h[i] = gru_init[i];
    if (i < 128) g_bar4[i] = 0;
}

// ---------------- K1: a_t, b_t, kinc_t ----------------
__global__ __launch_bounds__(256) void k_abk(
    const float* __restrict__ inp,
    const float* __restrict__ Wa, const float* __restrict__ ba,
    const float* __restrict__ Wb, const float* __restrict__ bb,
    const float* __restrict__ Wk, const float* __restrict__ bk)
{
    __shared__ float xs[8 * 516];
    int tid = threadIdx.x;
    int r0 = blockIdx.x * 8;
    #pragma unroll
    for (int c = 0; c < 4; c++) {
        int fi = c * 256 + tid;
        int r = fi >> 7, hq = fi & 127;
        float4 v = *(const float4*)&inp[(r0 + r) * 512 + hq * 4];
        *(float4*)&xs[r * 516 + hq * 4] = v;
    }
    __syncthreads();

    int r = tid >> 5, o = tid & 31;
    if (o >= 30) return;
    const float* wrow; float bias;
    if (o < 10)      { wrow = Wa + o * 512;        bias = ba[o]; }
    else if (o < 20) { wrow = Wb + (o - 10) * 512; bias = bb[o - 10]; }
    else             { wrow = Wk + (o - 20) * 512; bias = bk[o - 20]; }

    const float4* xp = (const float4*)&xs[r * 516];
    const float4* wp = (const float4*)wrow;
    float a0 = 0.f, a1 = 0.f, a2 = 0.f, a3 = 0.f;
    #pragma unroll 8
    for (int q = 0; q < 128; q++) {
        float4 x = xp[q];
        float4 w = __ldg(&wp[q]);
        a0 += x.x * w.x; a1 += x.y * w.y; a2 += x.z * w.z; a3 += x.w * w.w;
    }
    float v = expf((a0 + a1) + (a2 + a3) + bias);
    int row = r0 + r;
    if (o < 10)      g_a   [row * 10 + o]        = v;
    else if (o < 20) g_b2  [row * 10 + (o - 10)] = v * LOG2E;
    else             g_kinc[row * 10 + (o - 20)] = v;
}

// ---------------- K2: cumulative k_t ----------------
__global__ void k_cumsum(const float* __restrict__ att_init, float* __restrict__ out) {
    int j = blockIdx.x * 128 + threadIdx.x;
    if (j >= 640) return;
    float acc = att_init[j];
    #pragma unroll 8
    for (int t = 0; t < TS_; t++) {
        acc += g_kinc[t * 640 + j];
        g_kinc[t * 640 + j] = acc;
        out[OFF_ATTK + t * 640 + j] = acc;
    }
}

// ---------------- K3: phi ----------------
__global__ __launch_bounds__(512) void k_phi() {
    __shared__ float sa[10], sb[10], sk[10];
    int row = blockIdx.x;
    int tid = threadIdx.x;
    if (tid < 10)       sa[tid]      = g_a   [row * 10 + tid];
    else if (tid < 20)  sb[tid - 10] = g_b2  [row * 10 + tid - 10];
    else if (tid < 30)  sk[tid - 20] = g_kinc[row * 10 + tid - 20];
    __syncthreads();
    float s = (float)tid;
    float acc = 0.f;
    #pragma unroll
    for (int k = 0; k < 10; k++) {
        float d = sk[k] - s;
        float e = sb[k] * d * d;
        if (e < 30.f) acc += sa[k] * ex2f(-e);
    }
    g_phi[row * 512 + tid] = acc;
}

// ---------------- GEMM common: 128x128 tile, 8x8/thread, f32x2 ----------------
#define AST 264     // duplicated-A row stride (256 + 8 pad)
#define BST 132

// K4: w = phi @ c_inp  (per batch; A strided 32768, B [k][n] strided 32768)
__global__ __launch_bounds__(256, 2) void k_gemm_w(
    const float* __restrict__ c_inp, float* __restrict__ outw)
{
    __shared__ float As2[16 * AST];
    __shared__ float Bs [16 * BST];
    int tid = threadIdx.x;
    int b  = blockIdx.z;
    int m0 = blockIdx.y * 128, n0 = blockIdx.x * 128;

    int lrow = tid >> 2, lq = tid & 3;          // A loader
    const float* Ap0 = g_phi + b * 512 + (m0 + lrow) * 32768 + lq * 4;
    const float* Ap1 = Ap0 + 64 * 32768;
    int lk = tid >> 5, nq = tid & 31;           // B loader
    const float* Bp0 = c_inp + b * 512 + lk * 32768 + n0 + nq * 4;
    const float* Bp1 = Bp0 + 8 * 32768;

    float4 aR0 = *(const float4*)(Ap0);
    float4 aR1 = *(const float4*)(Ap1);
    float4 bR0 = *(const float4*)(Bp0);
    float4 bR1 = *(const float4*)(Bp1);

    int tx = tid & 15, ty = tid >> 4;
    u64 acc[8][4];
    #pragma unroll
    for (int i = 0; i < 8; i++)
        #pragma unroll
        for (int j = 0; j < 4; j++) acc[i][j] = 0ull;

    for (int kt = 0; kt < 32; kt++) {
        __syncthreads();
        {
            int m = 2 * lrow;
            *(u64*)&As2[(lq * 4 + 0) * AST + m]       = pack2(aR0.x, aR0.x);
            *(u64*)&As2[(lq * 4 + 1) * AST + m]       = pack2(aR0.y, aR0.y);
            *(u64*)&As2[(lq * 4 + 2) * AST + m]       = pack2(aR0.z, aR0.z);
            *(u64*)&As2[(lq * 4 + 3) * AST + m]       = pack2(aR0.w, aR0.w);
            *(u64*)&As2[(lq * 4 + 0) * AST + m + 128] = pack2(aR1.x, aR1.x);
            *(u64*)&As2[(lq * 4 + 1) * AST + m + 128] = pack2(aR1.y, aR1.y);
            *(u64*)&As2[(lq * 4 + 2) * AST + m + 128] = pack2(aR1.z, aR1.z);
            *(u64*)&As2[(lq * 4 + 3) * AST + m + 128] = pack2(aR1.w, aR1.w);
            *(float4*)&Bs[lk * BST + nq * 4]       = bR0;
            *(float4*)&Bs[(lk + 8) * BST + nq * 4] = bR1;
        }
        __syncthreads();
        if (kt < 31) {
            aR0 = *(const float4*)(Ap0 + (kt + 1) * 16);
            aR1 = *(const float4*)(Ap1 + (kt + 1) * 16);
            bR0 = *(const float4*)(Bp0 + (kt + 1) * 16 * 32768);
            bR1 = *(const float4*)(Bp1 + (kt + 1) * 16 * 32768);
        }
        #pragma unroll
        for (int kk = 0; kk < 16; kk++) {
            ulonglong2 a01 = *(const ulonglong2*)&As2[kk * AST + 8 * ty];
            ulonglong2 a23 = *(const ulonglong2*)&As2[kk * AST + 8 * ty + 4];
            ulonglong2 a45 = *(const ulonglong2*)&As2[kk * AST + 8 * ty + 128];
            ulonglong2 a67 = *(const ulonglong2*)&As2[kk * AST + 8 * ty + 132];
            ulonglong2 b01 = *(const ulonglong2*)&Bs[kk * BST + tx * 4];
            ulonglong2 b23 = *(const ulonglong2*)&Bs[kk * BST + tx * 4 + 64];
            u64 av[8] = {a01.x, a01.y, a23.x, a23.y, a45.x, a45.y, a67.x, a67.y};
            u64 bv[4] = {b01.x, b01.y, b23.x, b23.y};
            #pragma unroll
            for (int i = 0; i < 8; i++)
                #pragma unroll
                for (int j = 0; j < 4; j++)
                    acc[i][j] = ffma2(av[i], bv[j], acc[i][j]);
        }
    }
    float* C = outw + b * 512;
    #pragma unroll
    for (int i = 0; i < 8; i++) {
        int m = m0 + ((i < 4) ? (ty * 4 + i) : (ty * 4 + 64 + i - 4));
        float c0, c1, c2, c3;
        unpack2(acc[i][0], c0, c1); unpack2(acc[i][1], c2, c3);
        *(float4*)&C[m * 32768 + n0 + tx * 4] = make_float4(c0, c1, c2, c3);
        unpack2(acc[i][2], c0, c1); unpack2(acc[i][3], c2, c3);
        *(float4*)&C[m * 32768 + n0 + tx * 4 + 64] = make_float4(c0, c1, c2, c3);
    }
}

// K5: gi = w @ W_ih^T + b_ih   (A [m][k] ld512, B [n][k] ld512 -> both transposed loads)
__global__ __launch_bounds__(256, 2) void k_gemm_gi(
    const float* __restrict__ w, const float* __restrict__ W_ih,
    const float* __restrict__ b_ih)
{
    __shared__ float As2[16 * AST];
    __shared__ float Bs [16 * BST];
    int tid = threadIdx.x;
    int m0 = blockIdx.y * 128, n0 = blockIdx.x * 128;

    int lrow = tid >> 2, lq = tid & 3;
    const float* Ap0 = w + (m0 + lrow) * 512 + lq * 4;
    const float* Ap1 = Ap0 + 64 * 512;
    const float* Bp0 = W_ih + (n0 + lrow) * 512 + lq * 4;
    const float* Bp1 = Bp0 + 64 * 512;

    float4 aR0 = *(const float4*)(Ap0);
    float4 aR1 = *(const float4*)(Ap1);
    float4 bR0 = *(const float4*)(Bp0);
    float4 bR1 = *(const float4*)(Bp1);

    int tx = tid & 15, ty = tid >> 4;
    u64 acc[8][4];
    #pragma unroll
    for (int i = 0; i < 8; i++)
        #pragma unroll
        for (int j = 0; j < 4; j++) acc[i][j] = 0ull;

    for (int kt = 0; kt < 32; kt++) {
        __syncthreads();
        {
            int m = 2 * lrow;
            *(u64*)&As2[(lq * 4 + 0) * AST + m]       = pack2(aR0.x, aR0.x);
            *(u64*)&As2[(lq * 4 + 1) * AST + m]       = pack2(aR0.y, aR0.y);
            *(u64*)&As2[(lq * 4 + 2) * AST + m]       = pack2(aR0.z, aR0.z);
            *(u64*)&As2[(lq * 4 + 3) * AST + m]       = pack2(aR0.w, aR0.w);
            *(u64*)&As2[(lq * 4 + 0) * AST + m + 128] = pack2(aR1.x, aR1.x);
            *(u64*)&As2[(lq * 4 + 1) * AST + m + 128] = pack2(aR1.y, aR1.y);
            *(u64*)&As2[(lq * 4 + 2) * AST + m + 128] = pack2(aR1.z, aR1.z);
            *(u64*)&As2[(lq * 4 + 3) * AST + m + 128] = pack2(aR1.w, aR1.w);
            Bs[(lq * 4 + 0) * BST + lrow]       = bR0.x;
            Bs[(lq * 4 + 1) * BST + lrow]       = bR0.y;
            Bs[(lq * 4 + 2) * BST + lrow]       = bR0.z;
            Bs[(lq * 4 + 3) * BST + lrow]       = bR0.w;
            Bs[(lq * 4 + 0) * BST + lrow + 64]  = bR1.x;
            Bs[(lq * 4 + 1) * BST + lrow + 64]  = bR1.y;
            Bs[(lq * 4 + 2) * BST + lrow + 64]  = bR1.z;
            Bs[(lq * 4 + 3) * BST + lrow + 64]  = bR1.w;
        }
        __syncthreads();
        if (kt < 31) {
            aR0 = *(const float4*)(Ap0 + (kt + 1) * 16);
            aR1 = *(const float4*)(Ap1 + (kt + 1) * 16);
            bR0 = *(const float4*)(Bp0 + (kt + 1) * 16);
            bR1 = *(const float4*)(Bp1 + (kt + 1) * 16);
        }
        #pragma unroll
        for (int kk = 0; kk < 16; kk++) {
            ulonglong2 a01 = *(const ulonglong2*)&As2[kk * AST + 8 * ty];
            ulonglong2 a23 = *(const ulonglong2*)&As2[kk * AST + 8 * ty + 4];
            ulonglong2 a45 = *(const ulonglong2*)&As2[kk * AST + 8 * ty + 128];
            ulonglong2 a67 = *(const ulonglong2*)&As2[kk * AST + 8 * ty + 132];
            ulonglong2 b01 = *(const ulonglong2*)&Bs[kk * BST + tx * 4];
            ulonglong2 b23 = *(const ulonglong2*)&Bs[kk * BST + tx * 4 + 64];
            u64 av[8] = {a01.x, a01.y, a23.x, a23.y, a45.x, a45.y, a67.x, a67.y};
            u64 bv[4] = {b01.x, b01.y, b23.x, b23.y};
            #pragma unroll
            for (int i = 0; i < 8; i++)
                #pragma unroll
                for (int j = 0; j < 4; j++)
                    acc[i][j] = ffma2(av[i], bv[j], acc[i][j]);
        }
    }
    float4 bias0 = *(const float4*)&b_ih[n0 + tx * 4];
    float4 bias1 = *(const float4*)&b_ih[n0 + tx * 4 + 64];
    #pragma unroll
    for (int i = 0; i < 8; i++) {
        int m = m0 + ((i < 4) ? (ty * 4 + i) : (ty * 4 + 64 + i - 4));
        float c0, c1, c2, c3;
        unpack2(acc[i][0], c0, c1); unpack2(acc[i][1], c2, c3);
        *(float4*)&g_gi[m * 1536 + n0 + tx * 4] =
            make_float4(c0 + bias0.x, c1 + bias0.y, c2 + bias0.z, c3 + bias0.w);
        unpack2(acc[i][2], c0, c1); unpack2(acc[i][3], c2, c3);
        *(float4*)&g_gi[m * 1536 + n0 + tx * 4 + 64] =
            make_float4(c0 + bias1.x, c1 + bias1.y, c2 + bias1.z, c3 + bias1.w);
    }
}

// ---------------- K6: persistent sequential GRU ----------------
// grid (32 unit-groups, 4 batch-groups) x 128 threads
// thread: u = tid>>3 (16 local units), bp = tid&7, handles batches bp and bp+8
#define HS_ST 516
#define SMEM_GRU_BYTES ((48 + 16) * HS_ST * 4)

__global__ __launch_bounds__(128, 1) void k_gru(
    const float* __restrict__ W_hh, const float* __restrict__ b_hh,
    float* __restrict__ out)
{
    extern __shared__ float smem[];
    float* hs  = smem;               // [16][HS_ST]
    float* Wsm = smem + 16 * HS_ST;  // [48][HS_ST], row = gate*16 + u
    int tid = threadIdx.x;
    int ug = blockIdx.x, bg = blockIdx.y;

    // stage W_hh slice (48 rows x 512)
    for (int f = tid; f < 48 * 128; f += 128) {
        int rr = f >> 7, c = f & 127;
        int gate = rr >> 4, uu = rr & 15;
        float4 v = *(const float4*)&W_hh[(gate * 512 + ug * 16 + uu) * 512 + c * 4];
        *(float4*)&Wsm[rr * HS_ST + c * 4] = v;
    }

    int u  = tid >> 3;
    int bp = tid & 7;
    int gu  = ug * 16 + u;
    int gb0 = bg * 16 + bp;
    int gb1 = gb0 + 8;
    float bhr = b_hh[gu], bhz = b_hh[512 + gu], bhn = b_hh[1024 + gu];
    const float* wr = &Wsm[(0  + u) * HS_ST];
    const float* wz = &Wsm[(16 + u) * HS_ST];
    const float* wn = &Wsm[(32 + u) * HS_ST];
    const float* h0 = &hs[bp * HS_ST];
    const float* h1 = &hs[(bp + 8) * HS_ST];
    unsigned bar_target = 0;
    volatile unsigned* bar = &g_bar4[bg * 32];
    __syncthreads();

    for (int t = 0; t < TS_; t++) {
        // gi prefetch (6 scalars)
        const float* gp0 = g_gi + (t * 64 + gb0) * 1536 + gu;
        const float* gp1 = g_gi + (t * 64 + gb1) * 1536 + gu;
        float giR0 = __ldcs(gp0), giZ0 = __ldcs(gp0 + 512), giN0 = __ldcs(gp0 + 1024);
        float giR1 = __ldcs(gp1), giZ1 = __ldcs(gp1 + 512), giN1 = __ldcs(gp1 + 1024);

        // stage h_{t-1}: 16 rows x 512 = 2048 float4 / 128 threads
        const float4* src = (const float4*)(g_h + (t & 1) * 32768 + bg * 8192);
        #pragma unroll
        for (int c = 0; c < 16; c++) {
            int i = c * 128 + tid;
            float4 v = __ldcg(&src[i]);
            *(float4*)&hs[(i >> 7) * HS_ST + (i & 127) * 4] = v;
        }
        __syncthreads();

        u64 aR0 = 0, aZ0 = 0, aN0 = 0, aR1 = 0, aZ1 = 0, aN1 = 0;
        #pragma unroll 8
        for (int hh = 0; hh < 512; hh += 4) {
            ulonglong2 hv0 = *(const ulonglong2*)&h0[hh];
            ulonglong2 hv1 = *(const ulonglong2*)&h1[hh];
            ulonglong2 r2 = *(const ulonglong2*)&wr[hh];
            ulonglong2 z2 = *(const ulonglong2*)&wz[hh];
            ulonglong2 n2 = *(const ulonglong2*)&wn[hh];
            aR0 = ffma2(hv0.x, r2.x, aR0); aR0 = ffma2(hv0.y, r2.y, aR0);
            aZ0 = ffma2(hv0.x, z2.x, aZ0); aZ0 = ffma2(hv0.y, z2.y, aZ0);
            aN0 = ffma2(hv0.x, n2.x, aN0); aN0 = ffma2(hv0.y, n2.y, aN0);
            aR1 = ffma2(hv1.x, r2.x, aR1); aR1 = ffma2(hv1.y, r2.y, aR1);
            aZ1 = ffma2(hv1.x, z2.x, aZ1); aZ1 = ffma2(hv1.y, z2.y, aZ1);
            aN1 = ffma2(hv1.x, n2.x, aN1); aN1 = ffma2(hv1.y, n2.y, aN1);
        }
        float lo, hi;
        unpack2(aR0, lo, hi); float sR0 = lo + hi;
        unpack2(aZ0, lo, hi); float sZ0 = lo + hi;
        unpack2(aN0, lo, hi); float sN0 = lo + hi;
        unpack2(aR1, lo, hi); float sR1 = lo + hi;
        unpack2(aZ1, lo, hi); float sZ1 = lo + hi;
        unpack2(aN1, lo, hi); float sN1 = lo + hi;

        float hp0 = h0[gu & 511];
        float hp1 = h1[gu & 511];
        float r0 = sigmf(giR0 + sR0 + bhr);
        float z0 = sigmf(giZ0 + sZ0 + bhz);
        float n0v = tanhf(giN0 + r0 * (sN0 + bhn));
        float hn0 = (1.f - z0) * n0v + z0 * hp0;
        float r1 = sigmf(giR1 + sR1 + bhr);
        float z1 = sigmf(giZ1 + sZ1 + bhz);
        float n1v = tanhf(giN1 + r1 * (sN1 + bhn));
        float hn1 = (1.f - z1) * n1v + z1 * hp1;

        g_h[((t + 1) & 1) * 32768 + gb0 * 512 + gu] = hn0;
        g_h[((t + 1) & 1) * 32768 + gb1 * 512 + gu] = hn1;
        out[t * 32768 + gb0 * 512 + gu] = hn0;
        out[t * 32768 + gb1 * 512 + gu] = hn1;

        __threadfence();
        __syncthreads();
        if (tid == 0) {
            bar_target += 32;
            atomicAdd((unsigned*)bar, 1u);
            while (*bar < bar_target) { __nanosleep(64); }
        }
        __syncthreads();
    }
}

// ---------------- host ----------------
extern "C" void kernel_launch(void* const* d_in, const int* in_sizes, int n_in,
                              void* d_out, int out_size)
{
    const float* c_inp    = (const float*)d_in[0];
    const float* inp      = (const float*)d_in[1];
    const float* gru_init = (const float*)d_in[2];
    const float* att_init = (const float*)d_in[3];
    const float* Wa = (const float*)d_in[4];  const float* ba = (const float*)d_in[5];
    const float* Wb = (const float*)d_in[6];  const float* bb = (const float*)d_in[7];
    const float* Wk = (const float*)d_in[8];  const float* bk = (const float*)d_in[9];
    const float* W_ih = (const float*)d_in[10]; const float* b_ih = (const float*)d_in[11];
    const float* W_hh = (const float*)d_in[12]; const float* b_hh = (const float*)d_in[13];
    float* out = (float*)d_out;

    cudaFuncSetAttribute(k_gru, cudaFuncAttributeMaxDynamicSharedMemorySize, SMEM_GRU_BYTES);

    k_init   <<<32, 1024>>>(gru_init);
    k_abk    <<<2048, 256>>>(inp, Wa, ba, Wb, bb, Wk, bk);
    k_cumsum <<<5, 128>>>(att_init, out);
    k_phi    <<<16384, 512>>>();
    k_gemm_w <<<dim3(4, 2, 64), 256>>>(c_inp, out + OFF_ATTW);
    k_gemm_gi<<<dim3(12, 128), 256>>>(out + OFF_ATTW, W_ih, b_ih);
    k_gru    <<<dim3(32, 4), 128, SMEM_GRU_BYTES>>>(W_hh, b_hh, out);
}